// round 4
// baseline (speedup 1.0000x reference)
#include <cuda_runtime.h>
#include <math.h>

#define NBATCH 64
#define NPTS   500
#define DIM    2048
#define KCL    10
#define NITER  10
#define EPSV   1e-6f
#define NSPLIT 2
#define NROWC  (NPTS / NSPLIT)   // 250
#define TILE   64

// ---------------- persistent device scratch ----------------
__device__ float g_part[NBATCH * NSPLIT * KCL * DIM];
__device__ int   g_pcnt[NBATCH * NSPLIT * KCL];
__device__ int   g_assign[NBATCH * NPTS];

// ---------------- packed f32x2 helpers ----------------
__device__ __forceinline__ unsigned long long fma2(unsigned long long a,
                                                   unsigned long long b,
                                                   unsigned long long c) {
    unsigned long long d;
    asm("fma.rn.f32x2 %0, %1, %2, %3;" : "=l"(d) : "l"(a), "l"(b), "l"(c));
    return d;
}
__device__ __forceinline__ float2 unpack2(unsigned long long v) {
    float2 r;
    asm("mov.b64 {%0, %1}, %2;" : "=f"(r.x), "=f"(r.y) : "l"(v));
    return r;
}

// uniform-branch accumulate: a is warp-uniform; constant indices keep bacc in regs
__device__ __forceinline__ void accum_sel(float4* bacc, int a, float4 f) {
    switch (a) {
#define CASE(K) case K: bacc[K].x += f.x; bacc[K].y += f.y; \
                        bacc[K].z += f.z; bacc[K].w += f.w; break;
        CASE(0) CASE(1) CASE(2) CASE(3) CASE(4)
        CASE(5) CASE(6) CASE(7) CASE(8) CASE(9)
#undef CASE
        default: break;
    }
}

// ---------------- init ----------------
__global__ void init_kernel(const float* __restrict__ f) {
    int b = blockIdx.x / KCL, k = blockIdx.x % KCL;
    int d = threadIdx.x * 4;
    float4 v = *(const float4*)(f + ((size_t)(b * NPTS + k)) * DIM + d);
    *(float4*)(g_part + ((size_t)((b * 2 + 0) * KCL + k)) * DIM + d) = v;
    *(float4*)(g_part + ((size_t)((b * 2 + 1) * KCL + k)) * DIM + d) =
        make_float4(0.f, 0.f, 0.f, 0.f);
    if (threadIdx.x == 0) {
        g_pcnt[(b * 2 + 0) * KCL + k] = 1;
        g_pcnt[(b * 2 + 1) * KCL + k] = 0;
    }
}

// FMA block: same-acc updates spaced 4 apart
#define FMABLOCK(C0, C1, C2, C3)                                              \
    _Pragma("unroll")                                                         \
    for (int k = 0; k < KCL; k++) {                                           \
        ulonglong2 cc = *(const ulonglong2*)(scd + (size_t)k * DIM);          \
        acc[k][0] = fma2((C0).x, cc.x, acc[k][0]);                            \
        acc[k][1] = fma2((C1).x, cc.x, acc[k][1]);                            \
        acc[k][2] = fma2((C2).x, cc.x, acc[k][2]);                            \
        acc[k][3] = fma2((C3).x, cc.x, acc[k][3]);                            \
        acc[k][0] = fma2((C0).y, cc.y, acc[k][0]);                            \
        acc[k][1] = fma2((C1).y, cc.y, acc[k][1]);                            \
        acc[k][2] = fma2((C2).y, cc.y, acc[k][2]);                            \
        acc[k][3] = fma2((C3).y, cc.y, acc[k][3]);                            \
    }

// ---------------- fused iteration kernel ----------------
__global__ __launch_bounds__(512, 1) void iter_kernel(const float* __restrict__ feats) {
    extern __shared__ float smem[];
    float* sc     = smem;                  // [KCL][DIM]
    float* sacc   = smem + KCL * DIM;      // [KCL][DIM]
    float* schalf = sacc + KCL * DIM;      // [16]
    float* sinv   = schalf + 16;           // [16]
    int*   sa     = (int*)(sinv + 16);     // [TILE]
    int*   scnt   = sa + TILE;             // [16]

    int b = blockIdx.x >> 1, sp = blockIdx.x & 1;
    int tid = threadIdx.x, warp = tid >> 5, lane = tid & 31;
    float4 z4 = make_float4(0.f, 0.f, 0.f, 0.f);

    if (tid < KCL) {
        int c = g_pcnt[(b * 2 + 0) * KCL + tid] + g_pcnt[(b * 2 + 1) * KCL + tid];
        sinv[tid] = 1.0f / (float)(c > 1 ? c : 1);
        scnt[tid] = 0;
    }
    __syncthreads();

    {   // centroids = (part0 + part1) * inv ; zero accumulators
        const float4* q0 = (const float4*)(g_part + (size_t)(b * 2 + 0) * KCL * DIM);
        const float4* q1 = (const float4*)(g_part + (size_t)(b * 2 + 1) * KCL * DIM);
        for (int i = tid; i < KCL * DIM / 4; i += 512) {
            float4 a = q0[i], c = q1[i];
            float inv = sinv[i / (DIM / 4)];
            ((float4*)sc)[i] = make_float4((a.x + c.x) * inv, (a.y + c.y) * inv,
                                           (a.z + c.z) * inv, (a.w + c.w) * inv);
            ((float4*)sacc)[i] = z4;
        }
    }
    __syncthreads();

    if (warp < KCL) {
        float s = 0.f;
        for (int d = lane; d < DIM; d += 32) {
            float c = sc[warp * DIM + d];
            s = fmaf(c, c, s);
        }
        #pragma unroll
        for (int o = 16; o; o >>= 1) s += __shfl_xor_sync(0xffffffffu, s, o);
        if (lane == 0) schalf[warp] = 0.5f * s;
    }
    __syncthreads();

    const float* fb = feats + ((size_t)b * NPTS + (size_t)sp * NROWC) * DIM;
    int gabase = b * NPTS + sp * NROWC;
    int mywd = warp * 128 + lane * 4;

    for (int tbase = 0; tbase < NROWC; tbase += TILE) {
        // ---------- phase A: assign 4 rows per warp, depth-2 prefetch ----------
        int r0i = tbase + warp * 4;
        int i0 = min(r0i + 0, NROWC - 1);
        int i1 = min(r0i + 1, NROWC - 1);
        int i2 = min(r0i + 2, NROWC - 1);
        int i3 = min(r0i + 3, NROWC - 1);
        const float* p0 = fb + (size_t)i0 * DIM + lane * 4;
        const float* p1 = fb + (size_t)i1 * DIM + lane * 4;
        const float* p2 = fb + (size_t)i2 * DIM + lane * 4;
        const float* p3 = fb + (size_t)i3 * DIM + lane * 4;

        unsigned long long acc[KCL][4];
        #pragma unroll
        for (int k = 0; k < KCL; k++)
            #pragma unroll
            for (int r = 0; r < 4; r++) acc[k][r] = 0ull;

        ulonglong2 f0[2], f1[2], f2[2], f3[2];
        f0[0] = *(const ulonglong2*)(p0);        f0[1] = *(const ulonglong2*)(p0 + 128);
        f1[0] = *(const ulonglong2*)(p1);        f1[1] = *(const ulonglong2*)(p1 + 128);
        f2[0] = *(const ulonglong2*)(p2);        f2[1] = *(const ulonglong2*)(p2 + 128);
        f3[0] = *(const ulonglong2*)(p3);        f3[1] = *(const ulonglong2*)(p3 + 128);

        #pragma unroll 2
        for (int ch = 0; ch < 16; ch++) {
            int cur = ch & 1;
            ulonglong2 c0 = f0[cur], c1 = f1[cur], c2 = f2[cur], c3 = f3[cur];
            if (ch < 14) {
                int nofs = (ch + 2) * 128;
                f0[cur] = *(const ulonglong2*)(p0 + nofs);
                f1[cur] = *(const ulonglong2*)(p1 + nofs);
                f2[cur] = *(const ulonglong2*)(p2 + nofs);
                f3[cur] = *(const ulonglong2*)(p3 + nofs);
            }
            const float* scd = sc + ch * 128 + lane * 4;
            FMABLOCK(c0, c1, c2, c3);
        }

        float dot[KCL][4];
        #pragma unroll
        for (int k = 0; k < KCL; k++) {
            #pragma unroll
            for (int r = 0; r < 4; r++) {
                float2 v = unpack2(acc[k][r]);
                float s = v.x + v.y;
                #pragma unroll
                for (int o = 16; o; o >>= 1)
                    s += __shfl_xor_sync(0xffffffffu, s, o);
                dot[k][r] = s;
            }
        }
        #pragma unroll
        for (int r = 0; r < 4; r++) {
            if (lane == r) {
                float best = schalf[0] - dot[0][r];
                int bi = 0;
                #pragma unroll
                for (int k = 1; k < KCL; k++) {
                    float s = schalf[k] - dot[k][r];
                    if (s < best) { best = s; bi = k; }
                }
                bool valid = (r0i + r) < NROWC;
                sa[warp * 4 + r] = valid ? bi : -1;
                if (valid) g_assign[gabase + r0i + r] = bi;
            }
        }
        __syncthreads();

        // ---------- counts (warp 0) ----------
        if (warp == 0) {
            int a0 = sa[lane], a1 = sa[32 + lane];
            #pragma unroll
            for (int k = 0; k < KCL; k++) {
                unsigned m0 = __ballot_sync(0xffffffffu, a0 == k);
                unsigned m1 = __ballot_sync(0xffffffffu, a1 == k);
                if (lane == k) scnt[k] += __popc(m0) + __popc(m1);
            }
        }

        // ---------- phase B: sequential rows, uniform switch accumulate ----------
        {
            float4 bacc[KCL];
            #pragma unroll
            for (int k = 0; k < KCL; k++) bacc[k] = z4;

            const float* fsl = fb + (size_t)tbase * DIM + mywd;
            int lim = NROWC - tbase; if (lim > TILE) lim = TILE;

            #pragma unroll 1
            for (int n = 0; n < TILE; n += 4) {
                if (n >= lim) break;
                int n0 = n, n1 = min(n + 1, lim - 1);
                int n2 = min(n + 2, lim - 1), n3 = min(n + 3, lim - 1);
                float4 g0 = *(const float4*)(fsl + (size_t)n0 * DIM);
                float4 g1 = *(const float4*)(fsl + (size_t)n1 * DIM);
                float4 g2 = *(const float4*)(fsl + (size_t)n2 * DIM);
                float4 g3 = *(const float4*)(fsl + (size_t)n3 * DIM);
                accum_sel(bacc, sa[n0], g0);
                if (n + 1 < lim) accum_sel(bacc, sa[n + 1], g1);
                if (n + 2 < lim) accum_sel(bacc, sa[n + 2], g2);
                if (n + 3 < lim) accum_sel(bacc, sa[n + 3], g3);
            }

            #pragma unroll
            for (int k = 0; k < KCL; k++) {
                float4* ap = (float4*)(sacc + (size_t)k * DIM + mywd);
                float4 cur = *ap;
                cur.x += bacc[k].x; cur.y += bacc[k].y;
                cur.z += bacc[k].z; cur.w += bacc[k].w;
                *ap = cur;
            }
        }
        __syncthreads();
    }

    // write partials + counts for next iteration
    float* pb = g_part + (size_t)blockIdx.x * KCL * DIM;
    for (int i = tid; i < KCL * DIM / 4; i += 512)
        ((float4*)pb)[i] = ((const float4*)sacc)[i];
    if (tid < KCL) g_pcnt[blockIdx.x * KCL + tid] = scnt[tid];
}

// ---------------- final GeM pooling ----------------
__global__ __launch_bounds__(512) void final_kernel(const float* __restrict__ feats,
                                                    const float* __restrict__ pp,
                                                    float* __restrict__ out) {
    __shared__ int sa[NPTS];
    int b = blockIdx.x / KCL, k = blockIdx.x % KCL;
    int tid = threadIdx.x;
    for (int i = tid; i < NPTS; i += 512) sa[i] = g_assign[b * NPTS + i];
    __syncthreads();

    float pv = pp[0];
    bool p3 = (pv == 3.0f);
    const float* fb = feats + (size_t)b * NPTS * DIM + tid * 4;

    float ax = 0.f, ay = 0.f, az = 0.f, aw = 0.f;
    int cnt = 0;
    if (p3) {
        #pragma unroll 2
        for (int n = 0; n < NPTS; n++) {
            if (sa[n] == k) {
                cnt++;
                float4 f = *(const float4*)(fb + (size_t)n * DIM);
                float x = fmaxf(f.x, EPSV), y = fmaxf(f.y, EPSV);
                float z = fmaxf(f.z, EPSV), w = fmaxf(f.w, EPSV);
                ax += x * x * x; ay += y * y * y; az += z * z * z; aw += w * w * w;
            }
        }
    } else {
        for (int n = 0; n < NPTS; n++) {
            if (sa[n] == k) {
                cnt++;
                float4 f = *(const float4*)(fb + (size_t)n * DIM);
                ax += powf(fmaxf(f.x, EPSV), pv);
                ay += powf(fmaxf(f.y, EPSV), pv);
                az += powf(fmaxf(f.z, EPSV), pv);
                aw += powf(fmaxf(f.w, EPSV), pv);
            }
        }
    }

    float inv = 1.0f / (float)(cnt > 1 ? cnt : 1);
    size_t oi = (size_t)(b * KCL + k) * DIM + tid * 4;
    float4 o;
    if (cnt > 0) {
        if (p3) {
            o = make_float4(cbrtf(ax * inv), cbrtf(ay * inv),
                            cbrtf(az * inv), cbrtf(aw * inv));
        } else {
            float ip = 1.0f / pv;
            o = make_float4(powf(ax * inv, ip), powf(ay * inv, ip),
                            powf(az * inv, ip), powf(aw * inv, ip));
        }
    } else {
        o = make_float4(0.f, 0.f, 0.f, 0.f);
    }
    *(float4*)(out + oi) = o;
}

// ---------------- launch ----------------
extern "C" void kernel_launch(void* const* d_in, const int* in_sizes, int n_in,
                              void* d_out, int out_size) {
    const float* feats = (const float*)d_in[0];
    const float* p     = (const float*)d_in[1];
    float* out         = (float*)d_out;

    const int smem_iter = (2 * KCL * DIM + 32) * sizeof(float)
                        + (TILE + 16) * sizeof(int);
    cudaFuncSetAttribute(iter_kernel,
                         cudaFuncAttributeMaxDynamicSharedMemorySize, smem_iter);

    init_kernel<<<NBATCH * KCL, 512>>>(feats);
    for (int it = 0; it < NITER; it++)
        iter_kernel<<<NBATCH * NSPLIT, 512, smem_iter>>>(feats);
    final_kernel<<<NBATCH * KCL, 512>>>(feats, p, out);
}

// round 5
// speedup vs baseline: 1.1009x; 1.1009x over previous
#include <cuda_runtime.h>
#include <math.h>

#define NBATCH 64
#define NPTS   500
#define DIM    2048
#define KCL    10
#define NITER  10
#define EPSV   1e-6f
#define NSPLIT 2
#define NROWC  (NPTS / NSPLIT)   // 250
#define TROWS  48                // rows per tile (12 producer warps * 4)
#define NTILES ((NROWC + TROWS - 1) / TROWS)  // 6 (last tile = 10 rows)
#define NPWARP 12                // producer warps

// ---------------- persistent device scratch ----------------
__device__ float g_part[NBATCH * NSPLIT * KCL * DIM];
__device__ int   g_pcnt[NBATCH * NSPLIT * KCL];
__device__ int   g_assign[NBATCH * NPTS];

// ---------------- packed f32x2 helpers ----------------
__device__ __forceinline__ unsigned long long fma2(unsigned long long a,
                                                   unsigned long long b,
                                                   unsigned long long c) {
    unsigned long long d;
    asm("fma.rn.f32x2 %0, %1, %2, %3;" : "=l"(d) : "l"(a), "l"(b), "l"(c));
    return d;
}
__device__ __forceinline__ float2 unpack2(unsigned long long v) {
    float2 r;
    asm("mov.b64 {%0, %1}, %2;" : "=f"(r.x), "=f"(r.y) : "l"(v));
    return r;
}

// named producer/consumer barriers (id 0 reserved for __syncthreads)
#define BAR_ARRIVE(id) asm volatile("bar.arrive %0, %1;" :: "r"(id), "r"(512) : "memory")
#define BAR_WAIT(id)   asm volatile("bar.sync %0, %1;"   :: "r"(id), "r"(512) : "memory")

// ---------------- init ----------------
__global__ void init_kernel(const float* __restrict__ f) {
    int b = blockIdx.x / KCL, k = blockIdx.x % KCL;
    int d = threadIdx.x * 4;
    float4 v = *(const float4*)(f + ((size_t)(b * NPTS + k)) * DIM + d);
    *(float4*)(g_part + ((size_t)((b * 2 + 0) * KCL + k)) * DIM + d) = v;
    *(float4*)(g_part + ((size_t)((b * 2 + 1) * KCL + k)) * DIM + d) =
        make_float4(0.f, 0.f, 0.f, 0.f);
    if (threadIdx.x == 0) {
        g_pcnt[(b * 2 + 0) * KCL + k] = 1;
        g_pcnt[(b * 2 + 1) * KCL + k] = 0;
    }
}

// FMA block: same-acc updates spaced 4 apart
#define FMABLOCK(C0, C1, C2, C3)                                              \
    _Pragma("unroll")                                                         \
    for (int k = 0; k < KCL; k++) {                                           \
        ulonglong2 cc = *(const ulonglong2*)(scd + (size_t)k * DIM);          \
        acc[k][0] = fma2((C0).x, cc.x, acc[k][0]);                            \
        acc[k][1] = fma2((C1).x, cc.x, acc[k][1]);                            \
        acc[k][2] = fma2((C2).x, cc.x, acc[k][2]);                            \
        acc[k][3] = fma2((C3).x, cc.x, acc[k][3]);                            \
        acc[k][0] = fma2((C0).y, cc.y, acc[k][0]);                            \
        acc[k][1] = fma2((C1).y, cc.y, acc[k][1]);                            \
        acc[k][2] = fma2((C2).y, cc.y, acc[k][2]);                            \
        acc[k][3] = fma2((C3).y, cc.y, acc[k][3]);                            \
    }

// ---------------- fused iteration kernel (warp-specialized) ----------------
// grid = 128 (b, sp). 16 warps: 0-11 assign (producers), 12-15 update (consumers).
__global__ __launch_bounds__(512, 1) void iter_kernel(const float* __restrict__ feats) {
    extern __shared__ float smem[];
    float* sc     = smem;                  // [KCL][DIM] centroids
    float* sacc   = smem + KCL * DIM;      // [KCL][DIM] partial sums
    float* schalf = sacc + KCL * DIM;      // [16]
    float* sinv   = schalf + 16;           // [16]
    int*   sabuf  = (int*)(sinv + 16);     // [2][TROWS] double-buffered assignments
    int*   scnt   = sabuf + 2 * TROWS;     // [16]

    int b = blockIdx.x >> 1, sp = blockIdx.x & 1;
    int tid = threadIdx.x, warp = tid >> 5, lane = tid & 31;

    // ---- prologue (all warps) ----
    if (tid < KCL) {
        int c = g_pcnt[(b * 2 + 0) * KCL + tid] + g_pcnt[(b * 2 + 1) * KCL + tid];
        sinv[tid] = 1.0f / (float)(c > 1 ? c : 1);
        scnt[tid] = 0;
    }
    __syncthreads();
    {
        const float4* q0 = (const float4*)(g_part + (size_t)(b * 2 + 0) * KCL * DIM);
        const float4* q1 = (const float4*)(g_part + (size_t)(b * 2 + 1) * KCL * DIM);
        float4 z4 = make_float4(0.f, 0.f, 0.f, 0.f);
        for (int i = tid; i < KCL * DIM / 4; i += 512) {
            float4 a = q0[i], c = q1[i];
            float inv = sinv[i / (DIM / 4)];
            ((float4*)sc)[i] = make_float4((a.x + c.x) * inv, (a.y + c.y) * inv,
                                           (a.z + c.z) * inv, (a.w + c.w) * inv);
            ((float4*)sacc)[i] = z4;
        }
    }
    __syncthreads();
    if (warp < KCL) {
        float s = 0.f;
        for (int d = lane; d < DIM; d += 32) {
            float c = sc[warp * DIM + d];
            s = fmaf(c, c, s);
        }
        #pragma unroll
        for (int o = 16; o; o >>= 1) s += __shfl_xor_sync(0xffffffffu, s, o);
        if (lane == 0) schalf[warp] = 0.5f * s;
    }
    __syncthreads();

    const float* fb = feats + ((size_t)b * NPTS + (size_t)sp * NROWC) * DIM;
    int gabase = b * NPTS + sp * NROWC;

    if (warp < NPWARP) {
        // ================= PRODUCERS: assign =================
        for (int t = 0; t < NTILES; t++) {
            int p = t & 1;
            if (t >= 2) BAR_WAIT(3 + p);   // buffer p free?

            int r0i = t * TROWS + warp * 4;
            int i0 = min(r0i + 0, NROWC - 1);
            int i1 = min(r0i + 1, NROWC - 1);
            int i2 = min(r0i + 2, NROWC - 1);
            int i3 = min(r0i + 3, NROWC - 1);
            const float* p0 = fb + (size_t)i0 * DIM + lane * 4;
            const float* p1 = fb + (size_t)i1 * DIM + lane * 4;
            const float* p2 = fb + (size_t)i2 * DIM + lane * 4;
            const float* p3 = fb + (size_t)i3 * DIM + lane * 4;

            unsigned long long acc[KCL][4];
            #pragma unroll
            for (int k = 0; k < KCL; k++)
                #pragma unroll
                for (int r = 0; r < 4; r++) acc[k][r] = 0ull;

            // R1-proven shape: batched loads at loop head, then FMAs
            #pragma unroll 1
            for (int ch = 0; ch < 16; ch++) {
                int ofs = ch * 128;
                ulonglong2 c0 = *(const ulonglong2*)(p0 + ofs);
                ulonglong2 c1 = *(const ulonglong2*)(p1 + ofs);
                ulonglong2 c2 = *(const ulonglong2*)(p2 + ofs);
                ulonglong2 c3 = *(const ulonglong2*)(p3 + ofs);
                const float* scd = sc + ofs + lane * 4;
                FMABLOCK(c0, c1, c2, c3);
            }

            float dot[KCL][4];
            #pragma unroll
            for (int k = 0; k < KCL; k++) {
                #pragma unroll
                for (int r = 0; r < 4; r++) {
                    float2 v = unpack2(acc[k][r]);
                    float s = v.x + v.y;
                    #pragma unroll
                    for (int o = 16; o; o >>= 1)
                        s += __shfl_xor_sync(0xffffffffu, s, o);
                    dot[k][r] = s;
                }
            }
            #pragma unroll
            for (int r = 0; r < 4; r++) {
                if (lane == r) {
                    float best = schalf[0] - dot[0][r];
                    int bi = 0;
                    #pragma unroll
                    for (int k = 1; k < KCL; k++) {
                        float s = schalf[k] - dot[k][r];
                        if (s < best) { best = s; bi = k; }
                    }
                    bool valid = (r0i + r) < NROWC;
                    sabuf[p * TROWS + warp * 4 + r] = valid ? bi : -1;
                    if (valid) g_assign[gabase + r0i + r] = bi;
                }
            }
            __threadfence_block();
            BAR_ARRIVE(1 + p);             // buffer p full
        }
    } else {
        // ================= CONSUMERS: update =================
        int cw = warp - NPWARP;            // 0..3, owns d-slice cw*512
        int sbase = cw * 512;
        for (int t = 0; t < NTILES; t++) {
            int p = t & 1;
            BAR_WAIT(1 + p);               // wait buffer p full

            if (cw == 0) {                 // counts (warp 12)
                int a0 = sabuf[p * TROWS + lane];
                int a1 = (lane < TROWS - 32) ? sabuf[p * TROWS + 32 + lane] : -1;
                #pragma unroll
                for (int k = 0; k < KCL; k++) {
                    unsigned m0 = __ballot_sync(0xffffffffu, a0 == k);
                    unsigned m1 = __ballot_sync(0xffffffffu, a1 == k);
                    if (lane == k) scnt[k] += __popc(m0) + __popc(m1);
                }
            }

            const float* ftile = fb + (size_t)t * TROWS * DIM + sbase;
            #pragma unroll 2
            for (int n = 0; n < TROWS; n++) {
                int a = sabuf[p * TROWS + n];
                if ((unsigned)a < KCL) {
                    const float4* rp = (const float4*)(ftile + (size_t)n * DIM);
                    float4* ap = (float4*)(sacc + (size_t)a * DIM + sbase);
                    #pragma unroll
                    for (int j = 0; j < 4; j++) {
                        float4 g = rp[lane + 32 * j];
                        float4 cu = ap[lane + 32 * j];
                        cu.x += g.x; cu.y += g.y; cu.z += g.z; cu.w += g.w;
                        ap[lane + 32 * j] = cu;
                    }
                }
            }
            if (t + 2 < NTILES) BAR_ARRIVE(3 + p);   // buffer p free
        }
    }

    __syncthreads();
    // write partials + counts for next iteration
    float* pb = g_part + (size_t)blockIdx.x * KCL * DIM;
    for (int i = tid; i < KCL * DIM / 4; i += 512)
        ((float4*)pb)[i] = ((const float4*)sacc)[i];
    if (tid < KCL) g_pcnt[blockIdx.x * KCL + tid] = scnt[tid];
}

// ---------------- final GeM pooling ----------------
__global__ __launch_bounds__(512) void final_kernel(const float* __restrict__ feats,
                                                    const float* __restrict__ pp,
                                                    float* __restrict__ out) {
    __shared__ int sa[NPTS];
    int b = blockIdx.x / KCL, k = blockIdx.x % KCL;
    int tid = threadIdx.x;
    for (int i = tid; i < NPTS; i += 512) sa[i] = g_assign[b * NPTS + i];
    __syncthreads();

    float pv = pp[0];
    bool p3 = (pv == 3.0f);
    const float* fb = feats + (size_t)b * NPTS * DIM + tid * 4;

    float ax = 0.f, ay = 0.f, az = 0.f, aw = 0.f;
    int cnt = 0;
    if (p3) {
        #pragma unroll 2
        for (int n = 0; n < NPTS; n++) {
            if (sa[n] == k) {
                cnt++;
                float4 f = *(const float4*)(fb + (size_t)n * DIM);
                float x = fmaxf(f.x, EPSV), y = fmaxf(f.y, EPSV);
                float z = fmaxf(f.z, EPSV), w = fmaxf(f.w, EPSV);
                ax += x * x * x; ay += y * y * y; az += z * z * z; aw += w * w * w;
            }
        }
    } else {
        for (int n = 0; n < NPTS; n++) {
            if (sa[n] == k) {
                cnt++;
                float4 f = *(const float4*)(fb + (size_t)n * DIM);
                ax += powf(fmaxf(f.x, EPSV), pv);
                ay += powf(fmaxf(f.y, EPSV), pv);
                az += powf(fmaxf(f.z, EPSV), pv);
                aw += powf(fmaxf(f.w, EPSV), pv);
            }
        }
    }

    float inv = 1.0f / (float)(cnt > 1 ? cnt : 1);
    size_t oi = (size_t)(b * KCL + k) * DIM + tid * 4;
    float4 o;
    if (cnt > 0) {
        if (p3) {
            o = make_float4(cbrtf(ax * inv), cbrtf(ay * inv),
                            cbrtf(az * inv), cbrtf(aw * inv));
        } else {
            float ip = 1.0f / pv;
            o = make_float4(powf(ax * inv, ip), powf(ay * inv, ip),
                            powf(az * inv, ip), powf(aw * inv, ip));
        }
    } else {
        o = make_float4(0.f, 0.f, 0.f, 0.f);
    }
    *(float4*)(out + oi) = o;
}

// ---------------- launch ----------------
extern "C" void kernel_launch(void* const* d_in, const int* in_sizes, int n_in,
                              void* d_out, int out_size) {
    const float* feats = (const float*)d_in[0];
    const float* p     = (const float*)d_in[1];
    float* out         = (float*)d_out;

    const int smem_iter = (2 * KCL * DIM + 32) * sizeof(float)
                        + (2 * TROWS + 16) * sizeof(int);
    cudaFuncSetAttribute(iter_kernel,
                         cudaFuncAttributeMaxDynamicSharedMemorySize, smem_iter);

    init_kernel<<<NBATCH * KCL, 512>>>(feats);
    for (int it = 0; it < NITER; it++)
        iter_kernel<<<NBATCH * NSPLIT, 512, smem_iter>>>(feats);
    final_kernel<<<NBATCH * KCL, 512>>>(feats, p, out);
}

// round 6
// speedup vs baseline: 1.2567x; 1.1415x over previous
#include <cuda_runtime.h>
#include <math.h>

#define NBATCH 64
#define NPTS   500
#define DIM    2048
#define KCL    10
#define NITER  10
#define EPSV   1e-6f
#define NSPLIT 2
#define NROWC  (NPTS / NSPLIT)   // 250
#define TILE   64
#define NTILES ((NROWC + TILE - 1) / TILE)  // 4

// ---------------- persistent device scratch ----------------
__device__ float g_part[NBATCH * NSPLIT * KCL * DIM];
__device__ int   g_pcnt[NBATCH * NSPLIT * KCL];
__device__ int   g_assign[NBATCH * NPTS];

// ---------------- packed f32x2 helpers ----------------
__device__ __forceinline__ unsigned long long fma2(unsigned long long a,
                                                   unsigned long long b,
                                                   unsigned long long c) {
    unsigned long long d;
    asm("fma.rn.f32x2 %0, %1, %2, %3;" : "=l"(d) : "l"(a), "l"(b), "l"(c));
    return d;
}
__device__ __forceinline__ float2 unpack2(unsigned long long v) {
    float2 r;
    asm("mov.b64 {%0, %1}, %2;" : "=f"(r.x), "=f"(r.y) : "l"(v));
    return r;
}

// ---------------- init: partial slot0 = features[:, :K, :], cnt=1; slot1=0 ----
__global__ void init_kernel(const float* __restrict__ f) {
    int b = blockIdx.x / KCL, k = blockIdx.x % KCL;
    int d = threadIdx.x * 4;
    float4 v = *(const float4*)(f + ((size_t)(b * NPTS + k)) * DIM + d);
    *(float4*)(g_part + ((size_t)((b * 2 + 0) * KCL + k)) * DIM + d) = v;
    *(float4*)(g_part + ((size_t)((b * 2 + 1) * KCL + k)) * DIM + d) =
        make_float4(0.f, 0.f, 0.f, 0.f);
    if (threadIdx.x == 0) {
        g_pcnt[(b * 2 + 0) * KCL + k] = 1;
        g_pcnt[(b * 2 + 1) * KCL + k] = 0;
    }
}

// FMA block: same-acc updates spaced 4 apart (R2 order)
#define FMABLOCK(C0, C1, C2, C3)                                              \
    _Pragma("unroll")                                                         \
    for (int k = 0; k < KCL; k++) {                                           \
        ulonglong2 cc = *(const ulonglong2*)(scd + (size_t)k * DIM);          \
        acc[k][0] = fma2((C0).x, cc.x, acc[k][0]);                            \
        acc[k][1] = fma2((C1).x, cc.x, acc[k][1]);                            \
        acc[k][2] = fma2((C2).x, cc.x, acc[k][2]);                            \
        acc[k][3] = fma2((C3).x, cc.x, acc[k][3]);                            \
        acc[k][0] = fma2((C0).y, cc.y, acc[k][0]);                            \
        acc[k][1] = fma2((C1).y, cc.y, acc[k][1]);                            \
        acc[k][2] = fma2((C2).y, cc.y, acc[k][2]);                            \
        acc[k][3] = fma2((C3).y, cc.y, acc[k][3]);                            \
    }

// ---------------- fused: centroid build + assign + partial update ----------
// grid = 128 (b, sp), block = 512 (16 warps), ~165KB smem, 1 CTA/SM.
__global__ __launch_bounds__(512, 1) void iter_kernel(const float* __restrict__ feats) {
    extern __shared__ float smem[];
    float* sc      = smem;                    // [KCL][DIM] centroids
    float* sacc    = smem + KCL * DIM;        // [KCL][DIM] new partial sums
    float* schalf  = sacc + KCL * DIM;        // [16]
    float* sinv    = schalf + 16;             // [16]
    int*   sa      = (int*)(sinv + 16);       // [TILE]
    int*   ssorted = sa + TILE;               // [TILE]
    int*   soff    = ssorted + TILE;          // [12]
    int*   srun    = soff + 12;               // [10]
    int*   scnt    = srun + 10;               // [10]

    int b = blockIdx.x >> 1, sp = blockIdx.x & 1;
    int tid = threadIdx.x, warp = tid >> 5, lane = tid & 31;
    float4 z4 = make_float4(0.f, 0.f, 0.f, 0.f);

    // ---- fused reduce: centroids = (part0 + part1) * inv ----
    if (tid < KCL) {
        int c = g_pcnt[(b * 2 + 0) * KCL + tid] + g_pcnt[(b * 2 + 1) * KCL + tid];
        sinv[tid] = 1.0f / (float)(c > 1 ? c : 1);
        scnt[tid] = 0;
    }
    __syncthreads();
    {
        const float4* q0 = (const float4*)(g_part + (size_t)(b * 2 + 0) * KCL * DIM);
        const float4* q1 = (const float4*)(g_part + (size_t)(b * 2 + 1) * KCL * DIM);
        for (int i = tid; i < KCL * DIM / 4; i += 512) {
            float4 a = q0[i], c = q1[i];
            float inv = sinv[i >> 9];
            ((float4*)sc)[i] = make_float4((a.x + c.x) * inv, (a.y + c.y) * inv,
                                           (a.z + c.z) * inv, (a.w + c.w) * inv);
            ((float4*)sacc)[i] = z4;
        }
    }
    __syncthreads();

    if (warp < KCL) {
        float s = 0.f;
        for (int d = lane; d < DIM; d += 32) {
            float c = sc[warp * DIM + d];
            s = fmaf(c, c, s);
        }
        #pragma unroll
        for (int o = 16; o; o >>= 1) s += __shfl_xor_sync(0xffffffffu, s, o);
        if (lane == 0) schalf[warp] = 0.5f * s;
    }
    __syncthreads();

    const float* fb = feats + ((size_t)b * NPTS + (size_t)sp * NROWC) * DIM;
    int gabase = b * NPTS + sp * NROWC;
    int mywd = warp * 128 + lane * 4;

    for (int tile = 0; tile < NTILES; tile++) {
        int tbase = tile * TILE;
        int nrows = NROWC - tbase; if (nrows > TILE) nrows = TILE;

        // ---------- phase A: assign 4 rows per warp, depth-2 prefetch ----------
        int r0i = tbase + warp * 4;
        int i0 = min(r0i + 0, NROWC - 1);
        int i1 = min(r0i + 1, NROWC - 1);
        int i2 = min(r0i + 2, NROWC - 1);
        int i3 = min(r0i + 3, NROWC - 1);
        const float* p0 = fb + (size_t)i0 * DIM + lane * 4;
        const float* p1 = fb + (size_t)i1 * DIM + lane * 4;
        const float* p2 = fb + (size_t)i2 * DIM + lane * 4;
        const float* p3 = fb + (size_t)i3 * DIM + lane * 4;

        unsigned long long acc[KCL][4];
        #pragma unroll
        for (int k = 0; k < KCL; k++)
            #pragma unroll
            for (int r = 0; r < 4; r++) acc[k][r] = 0ull;

        ulonglong2 f0[2], f1[2], f2[2], f3[2];
        f0[0] = *(const ulonglong2*)(p0);      f0[1] = *(const ulonglong2*)(p0 + 128);
        f1[0] = *(const ulonglong2*)(p1);      f1[1] = *(const ulonglong2*)(p1 + 128);
        f2[0] = *(const ulonglong2*)(p2);      f2[1] = *(const ulonglong2*)(p2 + 128);
        f3[0] = *(const ulonglong2*)(p3);      f3[1] = *(const ulonglong2*)(p3 + 128);

        #pragma unroll 1
        for (int ch = 0; ch < 16; ch++) {
            int cur = ch & 1;
            ulonglong2 c0 = f0[cur], c1 = f1[cur], c2 = f2[cur], c3 = f3[cur];
            if (ch < 14) {
                int nofs = (ch + 2) * 128;
                f0[cur] = *(const ulonglong2*)(p0 + nofs);
                f1[cur] = *(const ulonglong2*)(p1 + nofs);
                f2[cur] = *(const ulonglong2*)(p2 + nofs);
                f3[cur] = *(const ulonglong2*)(p3 + nofs);
            }
            const float* scd = sc + ch * 128 + lane * 4;
            FMABLOCK(c0, c1, c2, c3);
        }

        // reduce + argmin
        float dot[KCL][4];
        #pragma unroll
        for (int k = 0; k < KCL; k++) {
            #pragma unroll
            for (int r = 0; r < 4; r++) {
                float2 v = unpack2(acc[k][r]);
                float s = v.x + v.y;
                #pragma unroll
                for (int o = 16; o; o >>= 1)
                    s += __shfl_xor_sync(0xffffffffu, s, o);
                dot[k][r] = s;
            }
        }
        #pragma unroll
        for (int r = 0; r < 4; r++) {
            if (lane == r) {
                float best = schalf[0] - dot[0][r];
                int bi = 0;
                #pragma unroll
                for (int k = 1; k < KCL; k++) {
                    float s = schalf[k] - dot[k][r];
                    if (s < best) { best = s; bi = k; }
                }
                bool valid = (r0i + r) < NROWC;
                sa[warp * 4 + r] = valid ? bi : -1;
                if (valid) g_assign[gabase + r0i + r] = bi;
            }
        }
        __syncthreads();

        // ---------- counting sort of the tile (warp 0, deterministic) ----------
        if (warp == 0) {
            int mycnt = 0;
            #pragma unroll
            for (int p = 0; p < 2; p++) {
                int n = p * 32 + lane;
                int a = (n < nrows) ? sa[n] : -1;
                #pragma unroll
                for (int k = 0; k < KCL; k++) {
                    unsigned m = __ballot_sync(0xffffffffu, a == k);
                    if (lane == k) mycnt += __popc(m);
                }
            }
            int v = (lane < KCL) ? mycnt : 0;
            #pragma unroll
            for (int o = 1; o < 16; o <<= 1) {
                int t = __shfl_up_sync(0xffffffffu, v, o);
                if (lane >= o) v += t;
            }
            int excl = v - ((lane < KCL) ? mycnt : 0);
            if (lane < KCL) { soff[lane] = excl; srun[lane] = excl; scnt[lane] += mycnt; }
            if (lane == KCL - 1) soff[KCL] = v;
            __syncwarp();
            #pragma unroll
            for (int p = 0; p < 2; p++) {
                int n = p * 32 + lane;
                int a = (n < nrows) ? sa[n] : -1;
                unsigned mybal = 0;
                #pragma unroll
                for (int k = 0; k < KCL; k++) {
                    unsigned m = __ballot_sync(0xffffffffu, a == k);
                    if (a == k) mybal = m;
                }
                if (a >= 0) {
                    int rank = __popc(mybal & ((1u << lane) - 1u));
                    ssorted[srun[a] + rank] = n;
                    if (rank == __popc(mybal) - 1) srun[a] += rank + 1;
                }
                __syncwarp();
            }
        }
        __syncthreads();

        // ---------- phase B: per-cluster sorted lists (rows hot in L2) ----------
        {
            const float* fsl = fb + (size_t)tbase * DIM + mywd;
            #pragma unroll
            for (int k = 0; k < KCL; k++) {
                int s0 = soff[k], s1 = soff[k + 1];
                if (s0 == s1) continue;
                float4 a4 = z4;
                int idx = s0;
                for (; idx + 2 <= s1; idx += 2) {
                    int na = ssorted[idx], nb = ssorted[idx + 1];
                    float4 fa = *(const float4*)(fsl + (size_t)na * DIM);
                    float4 fc = *(const float4*)(fsl + (size_t)nb * DIM);
                    a4.x += fa.x; a4.y += fa.y; a4.z += fa.z; a4.w += fa.w;
                    a4.x += fc.x; a4.y += fc.y; a4.z += fc.z; a4.w += fc.w;
                }
                if (idx < s1) {
                    int na = ssorted[idx];
                    float4 fa = *(const float4*)(fsl + (size_t)na * DIM);
                    a4.x += fa.x; a4.y += fa.y; a4.z += fa.z; a4.w += fa.w;
                }
                float4* ap = (float4*)(sacc + (size_t)k * DIM + mywd);
                float4 cur = *ap;
                cur.x += a4.x; cur.y += a4.y; cur.z += a4.z; cur.w += a4.w;
                *ap = cur;
            }
        }
        __syncthreads();
    }

    // write partials + counts for next iteration
    float* pb = g_part + (size_t)blockIdx.x * KCL * DIM;
    for (int i = tid; i < KCL * DIM / 4; i += 512)
        ((float4*)pb)[i] = ((const float4*)sacc)[i];
    if (tid < KCL) g_pcnt[blockIdx.x * KCL + tid] = scnt[tid];
}

// ---------------- final GeM pooling (empty cluster -> 0) ----------------
__global__ __launch_bounds__(512) void final_kernel(const float* __restrict__ feats,
                                                    const float* __restrict__ pp,
                                                    float* __restrict__ out) {
    __shared__ int sa[NPTS];
    int b = blockIdx.x / KCL, k = blockIdx.x % KCL;
    int tid = threadIdx.x;
    for (int i = tid; i < NPTS; i += 512) sa[i] = g_assign[b * NPTS + i];
    __syncthreads();

    float pv = pp[0];
    bool p3 = (pv == 3.0f);
    const float* fb = feats + (size_t)b * NPTS * DIM + tid * 4;

    float ax = 0.f, ay = 0.f, az = 0.f, aw = 0.f;
    int cnt = 0;
    if (p3) {
        #pragma unroll 2
        for (int n = 0; n < NPTS; n++) {
            if (sa[n] == k) {
                cnt++;
                float4 f = *(const float4*)(fb + (size_t)n * DIM);
                float x = fmaxf(f.x, EPSV), y = fmaxf(f.y, EPSV);
                float z = fmaxf(f.z, EPSV), w = fmaxf(f.w, EPSV);
                ax += x * x * x; ay += y * y * y; az += z * z * z; aw += w * w * w;
            }
        }
    } else {
        for (int n = 0; n < NPTS; n++) {
            if (sa[n] == k) {
                cnt++;
                float4 f = *(const float4*)(fb + (size_t)n * DIM);
                ax += powf(fmaxf(f.x, EPSV), pv);
                ay += powf(fmaxf(f.y, EPSV), pv);
                az += powf(fmaxf(f.z, EPSV), pv);
                aw += powf(fmaxf(f.w, EPSV), pv);
            }
        }
    }

    float inv = 1.0f / (float)(cnt > 1 ? cnt : 1);
    size_t oi = (size_t)(b * KCL + k) * DIM + tid * 4;
    float4 o;
    if (cnt > 0) {
        if (p3) {
            o = make_float4(cbrtf(ax * inv), cbrtf(ay * inv),
                            cbrtf(az * inv), cbrtf(aw * inv));
        } else {
            float ip = 1.0f / pv;
            o = make_float4(powf(ax * inv, ip), powf(ay * inv, ip),
                            powf(az * inv, ip), powf(aw * inv, ip));
        }
    } else {
        o = make_float4(0.f, 0.f, 0.f, 0.f);
    }
    *(float4*)(out + oi) = o;
}

// ---------------- launch ----------------
extern "C" void kernel_launch(void* const* d_in, const int* in_sizes, int n_in,
                              void* d_out, int out_size) {
    const float* feats = (const float*)d_in[0];
    const float* p     = (const float*)d_in[1];
    float* out         = (float*)d_out;

    const int smem_iter = (2 * KCL * DIM + 32) * sizeof(float)
                        + (TILE + TILE + 12 + 10 + 10) * sizeof(int);
    cudaFuncSetAttribute(iter_kernel,
                         cudaFuncAttributeMaxDynamicSharedMemorySize, smem_iter);

    init_kernel<<<NBATCH * KCL, 512>>>(feats);
    for (int it = 0; it < NITER; it++)
        iter_kernel<<<NBATCH * NSPLIT, 512, smem_iter>>>(feats);
    final_kernel<<<NBATCH * KCL, 512>>>(feats, p, out);
}